// round 9
// baseline (speedup 1.0000x reference)
#include <cuda_runtime.h>
#include <cuda_fp16.h>
#include <math.h>
#include <stdint.h>

#define NN 10000
#define EE 160000
#define TT 12
#define CC 512
#define HIDN 256
#define OUTD 12
#define CPAD 128

// ---------------- scratch ----------------
__device__ __align__(128) float g_deg[NN];
__device__ __align__(128) float g_dinv[NN];
__device__ __align__(128) float g_agg[NN * 48];       // [n][t*4+f]
__device__ __align__(128) float g_Weff[3 * 4 * CC];   // [gate][f][c]
__device__ __align__(128) float g_beff[3 * CC];
__device__ float g_probs[TT];
__device__ __align__(128) float g_H[NN * CC];
__device__ __align__(128) float g_ACC[NN * CC];
__device__ __align__(128) float g_Z[NN * CC];
__device__ __align__(128) float g_h1[NN * HIDN];
__device__ __align__(128) __half g_H_h[(NN + CPAD) * CC];
__device__ __align__(128) __half g_HR_h[(NN + CPAD) * CC];
__device__ __align__(128) __half g_Bzr_h[1024 * CC];  // [n][k]; n<512: Wzl_bot col n, else Wrl_bot
__device__ __align__(128) __half g_Bh_h[CC * CC];     // [n][k]; Whl_bot transposed

// ---------------- helpers ----------------
__device__ __forceinline__ unsigned f2tf(float f) {
    unsigned u; asm("cvt.rna.tf32.f32 %0, %1;" : "=r"(u) : "f"(f)); return u;
}
__device__ __forceinline__ uint32_t s2u(const void* p) {
    uint32_t a;
    asm("{ .reg .u64 t; cvta.to.shared.u64 t, %1; cvt.u32.u64 %0, t; }" : "=r"(a) : "l"(p));
    return a;
}
__device__ __forceinline__ void cpa16(uint32_t dst, const void* src) {
    asm volatile("cp.async.cg.shared.global [%0], [%1], 16;" :: "r"(dst), "l"(src));
}
__device__ __forceinline__ void cpa_commit() { asm volatile("cp.async.commit_group;"); }
template<int W> __device__ __forceinline__ void cpa_wait() {
    asm volatile("cp.async.wait_group %0;" :: "n"(W) : "memory");
}
__device__ __forceinline__ void mma_f16(float* c, const uint32_t* a, const uint32_t* b) {
    asm volatile(
        "mma.sync.aligned.m16n8k16.row.col.f32.f16.f16.f32 "
        "{%0,%1,%2,%3}, {%4,%5,%6,%7}, {%8,%9}, {%0,%1,%2,%3};\n"
        : "+f"(c[0]), "+f"(c[1]), "+f"(c[2]), "+f"(c[3])
        : "r"(a[0]), "r"(a[1]), "r"(a[2]), "r"(a[3]), "r"(b[0]), "r"(b[1]));
}
__device__ __forceinline__ void mma_tf32(float* c, const unsigned* a, const unsigned* b) {
    asm volatile(
        "mma.sync.aligned.m16n8k8.row.col.f32.tf32.tf32.f32 "
        "{%0,%1,%2,%3}, {%4,%5,%6,%7}, {%8,%9}, {%0,%1,%2,%3};\n"
        : "+f"(c[0]), "+f"(c[1]), "+f"(c[2]), "+f"(c[3])
        : "r"(a[0]), "r"(a[1]), "r"(a[2]), "r"(a[3]), "r"(b[0]), "r"(b[1]));
}
#define LDM4(r, a) \
    asm volatile("ldmatrix.sync.aligned.m8n8.x4.shared.b16 {%0,%1,%2,%3}, [%4];" \
                 : "=r"((r)[0]), "=r"((r)[1]), "=r"((r)[2]), "=r"((r)[3]) : "r"(a))

// fast accurate tanh: 1 MUFU (ex2) + Newton reciprocal, err ~1e-6
__device__ __forceinline__ float ftanh(float v) {
    v = fminf(fmaxf(v, -9.0f), 9.0f);
    float u; asm("ex2.approx.f32 %0, %1;" : "=f"(u) : "f"(v * 2.8853900817779268f));
    float d = 1.0f + u;
    float y = __uint_as_float(0x7EF311C3u - __float_as_uint(d));
    y = y * (2.0f - d * y);
    y = y * (2.0f - d * y);
    y = y * (2.0f - d * y);
    return 1.0f - 2.0f * y;
}
// paired sigmoid via tanh.approx.f16x2: 1 MUFU for 2 values
__device__ __forceinline__ void sigmoid2(float v0, float v1, float& s0, float& s1) {
    __half2 hv = __floats2half2_rn(0.5f * v0, 0.5f * v1);
    uint32_t ti;
    asm("tanh.approx.f16x2 %0, %1;" : "=r"(ti) : "r"(*(uint32_t*)&hv));
    __half2 th = *(__half2*)&ti;
    s0 = 0.5f * __low2float(th) + 0.5f;
    s1 = 0.5f * __high2float(th) + 0.5f;
}

// ---------------- prep kernels ----------------
__global__ void init_deg_kernel() {
    int i = blockIdx.x * blockDim.x + threadIdx.x;
    if (i < NN) g_deg[i] = 1.0f;
}
__global__ void deg_edges_kernel(const int* __restrict__ ei, const float* __restrict__ ea) {
    int e = blockIdx.x * blockDim.x + threadIdx.x;
    if (e < EE) atomicAdd(&g_deg[ei[EE + e]], ea[e]);
}
__global__ void dinv_kernel() {
    int i = blockIdx.x * blockDim.x + threadIdx.x;
    if (i < NN) g_dinv[i] = rsqrtf(fmaxf(g_deg[i], 1e-12f));
}
__global__ void agg_init_kernel(const float* __restrict__ x) {
    int idx = blockIdx.x * blockDim.x + threadIdx.x;
    if (idx >= NN * 48) return;
    int n = idx / 48, k = idx % 48, t = k >> 2, f = k & 3;
    float di = g_dinv[n];
    g_agg[idx] = di * di * x[n * 48 + f * 12 + t];
}
__global__ void agg_edges_kernel(const float* __restrict__ x,
                                 const int* __restrict__ ei,
                                 const float* __restrict__ ea) {
    long long idx = (long long)blockIdx.x * blockDim.x + threadIdx.x;
    if (idx >= (long long)EE * 48) return;
    int e = (int)(idx / 48), k = (int)(idx % 48), t = k >> 2, f = k & 3;
    int s = ei[e], d = ei[EE + e];
    float nrm = g_dinv[s] * ea[e] * g_dinv[d];
    atomicAdd(&g_agg[(long long)d * 48 + k], nrm * x[s * 48 + f * 12 + t]);
}
__global__ void weff_kernel(const float* __restrict__ Wg, const float* __restrict__ bg,
                            const float* __restrict__ Wl, const float* __restrict__ bl,
                            int gate) {
    int idx = blockIdx.x * blockDim.x + threadIdx.x;
    if (idx >= 5 * CC) return;
    int row = idx / CC, c = idx % CC;
    if (row < 4) {
        float s = 0.f;
        for (int k = 0; k < CC; ++k) s += Wg[row * CC + k] * Wl[k * CC + c];
        g_Weff[gate * 4 * CC + row * CC + c] = s;
    } else {
        float s = bl[c];
        for (int k = 0; k < CC; ++k) s += bg[k] * Wl[k * CC + c];
        g_beff[gate * CC + c] = s;
    }
}
__global__ void softmax_att_kernel(const float* __restrict__ att) {
    if (threadIdx.x == 0 && blockIdx.x == 0) {
        float m = -1e30f;
        for (int t = 0; t < TT; ++t) m = fmaxf(m, att[t]);
        float s = 0.f, e[TT];
        for (int t = 0; t < TT; ++t) { e[t] = expf(att[t] - m); s += e[t]; }
        float inv = 1.0f / s;
        for (int t = 0; t < TT; ++t) g_probs[t] = e[t] * inv;
    }
}
__global__ void zero_HA_kernel() {
    int i = blockIdx.x * blockDim.x + threadIdx.x;
    if (i < NN * CC) {
        g_H[i] = 0.f; g_ACC[i] = 0.f;
        g_H_h[i] = __float2half(0.f);
    }
}
__global__ void prep_Bzr_h_kernel(const float* __restrict__ Wzl, const float* __restrict__ Wrl) {
    int idx = blockIdx.x * blockDim.x + threadIdx.x;
    if (idx >= 1024 * CC) return;
    int n = idx / CC, k = idx % CC;
    const float* W = (n < CC) ? Wzl : Wrl;
    g_Bzr_h[idx] = __float2half_rn(W[(CC + k) * CC + (n & (CC - 1))]);
}
__global__ void prep_Bh_h_kernel(const float* __restrict__ Whl) {
    int idx = blockIdx.x * blockDim.x + threadIdx.x;
    if (idx >= CC * CC) return;
    int n = idx / CC, k = idx % CC;
    g_Bh_h[idx] = __float2half_rn(Whl[(CC + k) * CC + n]);
}

// ---------------- fp16 GEMM mainloop (3-stage cp.async, ldmatrix) ----------------
// Tile 128x128x32. SMEM row = 32 halfs + pad -> 80B stride (RS=20 words).
// Per stage: A 10240B + B 10240B; 3 stages dynamic = 61440B.
#define STAGE_BYTES 20480
#define SMEM_GEMM (3 * STAGE_BYTES)

__device__ __forceinline__ void mainloop_f16(
    uint32_t sb, const __half* __restrict__ Asrc, const __half* __restrict__ Bsrc,
    int m0, int n0, int tid, float (*cacc)[8][4]) {

    const int lane = tid & 31, warp = tid >> 5;
    const int wm = warp & 3, wn = warp >> 2;

#pragma unroll
    for (int i = 0; i < 2; ++i)
#pragma unroll
        for (int j = 0; j < 8; ++j)
#pragma unroll
            for (int q = 0; q < 4; ++q) cacc[i][j][q] = 0.f;

    // staging addresses (two 16B tasks per thread per operand)
    const int r0 = tid >> 2, ch = tid & 3;
    const int r1 = r0 + 64;
    const uint32_t stOff0 = (uint32_t)(r0 * 80 + ch * 16);
    const uint32_t stOff1 = (uint32_t)(r1 * 80 + ch * 16);
    const __half* aP0 = Asrc + (size_t)(m0 + r0) * CC + ch * 8;
    const __half* aP1 = Asrc + (size_t)(m0 + r1) * CC + ch * 8;
    const __half* bP0 = Bsrc + (size_t)(n0 + r0) * CC + ch * 8;
    const __half* bP1 = Bsrc + (size_t)(n0 + r1) * CC + ch * 8;

    // ldmatrix lane offsets
    const uint32_t aoff0 = (uint32_t)((wm * 32 + (lane & 15)) * 80 + ((lane >> 4) << 4));
    const uint32_t aoff1 = aoff0 + 16 * 80;
    const uint32_t boff = (uint32_t)((wn * 64 + (lane & 7) + ((lane & 16) >> 1)) * 80
                                     + (((lane >> 3) & 1) << 4));

#define STAGE(s, kt) do { \
        uint32_t ab_ = sb + (s) * STAGE_BYTES; \
        uint32_t bb_ = ab_ + 10240; \
        int k0_ = (kt) * 32; \
        cpa16(ab_ + stOff0, aP0 + k0_); \
        cpa16(ab_ + stOff1, aP1 + k0_); \
        cpa16(bb_ + stOff0, bP0 + k0_); \
        cpa16(bb_ + stOff1, bP1 + k0_); \
        cpa_commit(); \
    } while (0)

    STAGE(0, 0);
    STAGE(1, 1);

    for (int kt = 0; kt < 16; ++kt) {
        if (kt < 15) cpa_wait<1>(); else cpa_wait<0>();
        __syncthreads();
        if (kt + 2 < 16) STAGE((kt + 2) % 3, kt + 2);

        uint32_t ab = sb + (kt % 3) * STAGE_BYTES;
        uint32_t bb = ab + 10240;
#pragma unroll
        for (int kc = 0; kc < 2; ++kc) {
            const uint32_t kb = kc * 32;
            uint32_t a[2][4], b[4][4];
            LDM4(a[0], ab + aoff0 + kb);
            LDM4(a[1], ab + aoff1 + kb);
            LDM4(b[0], bb + boff + kb);
            LDM4(b[1], bb + boff + kb + 16 * 80);
            LDM4(b[2], bb + boff + kb + 32 * 80);
            LDM4(b[3], bb + boff + kb + 48 * 80);
#pragma unroll
            for (int ms = 0; ms < 2; ++ms)
#pragma unroll
                for (int ns = 0; ns < 8; ++ns)
                    mma_f16(cacc[ms][ns], a[ms], &b[ns >> 1][(ns & 1) * 2]);
        }
    }
#undef STAGE
}

// z & r fused: grid (79, 8); by<4 -> z gate, by>=4 -> r gate
__global__ __launch_bounds__(256, 2) void gemm_zr_f16(int t) {
    extern __shared__ char dsm[];
    const int tid = threadIdx.x;
    const int lane = tid & 31, warp = tid >> 5;
    const int wm = warp & 3, wn = warp >> 2;
    const int g = lane >> 2, tig = lane & 3;
    const int m0 = blockIdx.x * 128;
    const int n0 = blockIdx.y * 128;

    float cacc[2][8][4];
    mainloop_f16(s2u(dsm), g_H_h, g_Bzr_h, m0, n0, tid, cacc);

    const int gate = n0 >> 9;
    const int c0 = n0 & (CC - 1);
    const float* We = g_Weff + gate * 4 * CC;
    const float* be = g_beff + gate * CC;

#pragma unroll
    for (int ms = 0; ms < 2; ++ms) {
#pragma unroll
        for (int hf = 0; hf < 2; ++hf) {
            int m = m0 + wm * 32 + ms * 16 + g + hf * 8;
            if (m >= NN) continue;
            float4 xa = *(const float4*)(g_agg + (size_t)m * 48 + t * 4);
            size_t rbase = (size_t)m * CC;
#pragma unroll
            for (int ns = 0; ns < 8; ++ns) {
                int ci = c0 + wn * 64 + ns * 8 + tig * 2;
                float2 b2 = *(const float2*)(be + ci);
                float2 w0 = *(const float2*)(We + ci);
                float2 w1 = *(const float2*)(We + CC + ci);
                float2 w2 = *(const float2*)(We + 2 * CC + ci);
                float2 w3 = *(const float2*)(We + 3 * CC + ci);
                float v0 = cacc[ms][ns][hf * 2 + 0] + b2.x
                         + xa.x * w0.x + xa.y * w1.x + xa.z * w2.x + xa.w * w3.x;
                float v1 = cacc[ms][ns][hf * 2 + 1] + b2.y
                         + xa.x * w0.y + xa.y * w1.y + xa.z * w2.y + xa.w * w3.y;
                float s0, s1;
                sigmoid2(v0, v1, s0, s1);
                if (gate == 0) {
                    float2 o; o.x = s0; o.y = s1;
                    *(float2*)(g_Z + rbase + ci) = o;
                } else {
                    float2 h2 = *(const float2*)(g_H + rbase + ci);
                    *(__half2*)(g_HR_h + rbase + ci) = __floats2half2_rn(h2.x * s0, h2.y * s1);
                }
            }
        }
    }
}

// h gate: grid (79, 4)
__global__ __launch_bounds__(256, 2) void gemm_h_f16(int t) {
    extern __shared__ char dsm[];
    const int tid = threadIdx.x;
    const int lane = tid & 31, warp = tid >> 5;
    const int wm = warp & 3, wn = warp >> 2;
    const int g = lane >> 2, tig = lane & 3;
    const int m0 = blockIdx.x * 128;
    const int n0 = blockIdx.y * 128;

    float cacc[2][8][4];
    mainloop_f16(s2u(dsm), g_HR_h, g_Bh_h, m0, n0, tid, cacc);

    const float* We = g_Weff + 2 * 4 * CC;
    const float* be = g_beff + 2 * CC;
    float p = g_probs[t];

#pragma unroll
    for (int ms = 0; ms < 2; ++ms) {
#pragma unroll
        for (int hf = 0; hf < 2; ++hf) {
            int m = m0 + wm * 32 + ms * 16 + g + hf * 8;
            if (m >= NN) continue;
            float4 xa = *(const float4*)(g_agg + (size_t)m * 48 + t * 4);
            size_t rbase = (size_t)m * CC;
#pragma unroll
            for (int ns = 0; ns < 8; ++ns) {
                int ci = n0 + wn * 64 + ns * 8 + tig * 2;
                float2 b2 = *(const float2*)(be + ci);
                float2 w0 = *(const float2*)(We + ci);
                float2 w1 = *(const float2*)(We + CC + ci);
                float2 w2 = *(const float2*)(We + 2 * CC + ci);
                float2 w3 = *(const float2*)(We + 3 * CC + ci);
                float v0 = cacc[ms][ns][hf * 2 + 0] + b2.x
                         + xa.x * w0.x + xa.y * w1.x + xa.z * w2.x + xa.w * w3.x;
                float v1 = cacc[ms][ns][hf * 2 + 1] + b2.y
                         + xa.x * w0.y + xa.y * w1.y + xa.z * w2.y + xa.w * w3.y;
                float ht0 = ftanh(v0), ht1 = ftanh(v1);
                float2 z2 = *(const float2*)(g_Z + rbase + ci);
                float2 h2 = *(const float2*)(g_H + rbase + ci);
                float2 Hn;
                Hn.x = z2.x * h2.x + (1.f - z2.x) * ht0;
                Hn.y = z2.y * h2.y + (1.f - z2.y) * ht1;
                *(float2*)(g_H + rbase + ci) = Hn;
                *(__half2*)(g_H_h + rbase + ci) = __floats2half2_rn(Hn.x, Hn.y);
                float2 a2 = *(const float2*)(g_ACC + rbase + ci);
                a2.x += p * Hn.x; a2.y += p * Hn.y;
                *(float2*)(g_ACC + rbase + ci) = a2;
            }
        }
    }
}

// ---------------- head (tf32 mma.sync, known-good) ----------------
#define SA 133
#define SB 136
__global__ __launch_bounds__(256, 2) void head1_tc(const float* __restrict__ W1,
                                                   const float* __restrict__ b1) {
    __shared__ unsigned As[32 * SA];
    __shared__ unsigned Bs[32 * SB];
    const int tid = threadIdx.x;
    const int lane = tid & 31, warp = tid >> 5;
    const int wm = warp & 3, wn = warp >> 2;
    const int g = lane >> 2, tig = lane & 3;
    const int m0 = blockIdx.x * 128;
    const int n0 = blockIdx.y * 128;

    float c[2][8][4];
#pragma unroll
    for (int i = 0; i < 2; ++i)
#pragma unroll
        for (int j = 0; j < 8; ++j)
#pragma unroll
            for (int q = 0; q < 4; ++q) c[i][j][q] = 0.f;

    const int arow = tid >> 3;
    const int acg = (tid & 7) * 4;
    const int bc4 = (tid & 31) * 4;
    const int bkr = tid >> 5;

    for (int k0 = 0; k0 < CC; k0 += 32) {
#pragma unroll
        for (int it = 0; it < 4; ++it) {
            int mloc = arow + it * 32;
            int m = m0 + mloc;
            float4 v = make_float4(0.f, 0.f, 0.f, 0.f);
            if (m < NN) v = *(const float4*)(g_ACC + (size_t)m * CC + k0 + acg);
            As[(acg + 0) * SA + mloc] = f2tf(fmaxf(v.x, 0.f));
            As[(acg + 1) * SA + mloc] = f2tf(fmaxf(v.y, 0.f));
            As[(acg + 2) * SA + mloc] = f2tf(fmaxf(v.z, 0.f));
            As[(acg + 3) * SA + mloc] = f2tf(fmaxf(v.w, 0.f));
        }
#pragma unroll
        for (int it = 0; it < 4; ++it) {
            int k = bkr + it * 8;
            float4 v = *(const float4*)(W1 + (size_t)(k0 + k) * HIDN + n0 + bc4);
            Bs[k * SB + bc4 + 0] = f2tf(v.x);
            Bs[k * SB + bc4 + 1] = f2tf(v.y);
            Bs[k * SB + bc4 + 2] = f2tf(v.z);
            Bs[k * SB + bc4 + 3] = f2tf(v.w);
        }
        __syncthreads();
#pragma unroll
        for (int kc = 0; kc < 4; ++kc) {
            const int kb = kc * 8;
            unsigned a[2][4], b[8][2];
#pragma unroll
            for (int ms = 0; ms < 2; ++ms) {
                int mb = wm * 32 + ms * 16 + g;
                a[ms][0] = As[(kb + tig) * SA + mb];
                a[ms][1] = As[(kb + tig) * SA + mb + 8];
                a[ms][2] = As[(kb + tig + 4) * SA + mb];
                a[ms][3] = As[(kb + tig + 4) * SA + mb + 8];
            }
#pragma unroll
            for (int ns = 0; ns < 8; ++ns) {
                int nb = wn * 64 + ns * 8 + g;
                b[ns][0] = Bs[(kb + tig) * SB + nb];
                b[ns][1] = Bs[(kb + tig + 4) * SB + nb];
            }
#pragma unroll
            for (int ms = 0; ms < 2; ++ms)
#pragma unroll
                for (int ns = 0; ns < 8; ++ns) mma_tf32(c[ms][ns], a[ms], b[ns]);
        }
        __syncthreads();
    }
#pragma unroll
    for (int ms = 0; ms < 2; ++ms) {
#pragma unroll
        for (int half = 0; half < 2; ++half) {
            int m = m0 + wm * 32 + ms * 16 + g + half * 8;
            if (m >= NN) continue;
#pragma unroll
            for (int ns = 0; ns < 8; ++ns) {
                int ncol = n0 + wn * 64 + ns * 8 + tig * 2;
#pragma unroll
                for (int j = 0; j < 2; ++j) {
                    int ci = ncol + j;
                    float v = fmaxf(c[ms][ns][half * 2 + j] + b1[ci], 0.f);
                    g_h1[(size_t)m * HIDN + ci] = v;
                }
            }
        }
    }
}

__global__ void head2_kernel(const float* __restrict__ W2, const float* __restrict__ b2,
                             float* __restrict__ out) {
    int idx = blockIdx.x * blockDim.x + threadIdx.x;
    if (idx >= NN * OUTD) return;
    int n = idx / OUTD, o = idx % OUTD;
    float s = b2[o];
    const float* hrow = g_h1 + (size_t)n * HIDN;
#pragma unroll 8
    for (int k = 0; k < HIDN; ++k) s += hrow[k] * W2[k * OUTD + o];
    out[idx] = s;
}

__global__ void copy_acc_kernel(float* __restrict__ out) {
    int i = blockIdx.x * blockDim.x + threadIdx.x;
    if (i < NN * CC) out[NN * OUTD + i] = g_ACC[i];
}

// ---------------- launch ----------------
extern "C" void kernel_launch(void* const* d_in, const int* in_sizes, int n_in,
                              void* d_out, int out_size) {
    const float* x   = (const float*)d_in[0];
    const int*   ei  = (const int*)d_in[1];
    const float* ea  = (const float*)d_in[2];
    const float* att = (const float*)d_in[3];
    const float* Wzg = (const float*)d_in[4];  const float* bzg = (const float*)d_in[5];
    const float* Wzl = (const float*)d_in[6];  const float* bzl = (const float*)d_in[7];
    const float* Wrg = (const float*)d_in[8];  const float* brg = (const float*)d_in[9];
    const float* Wrl = (const float*)d_in[10]; const float* brl = (const float*)d_in[11];
    const float* Whg = (const float*)d_in[12]; const float* bhg = (const float*)d_in[13];
    const float* Whl = (const float*)d_in[14]; const float* bhl = (const float*)d_in[15];
    const float* W1  = (const float*)d_in[16]; const float* b1  = (const float*)d_in[17];
    const float* W2  = (const float*)d_in[18]; const float* b2  = (const float*)d_in[19];
    float* out = (float*)d_out;

    cudaFuncSetAttribute(gemm_zr_f16, cudaFuncAttributeMaxDynamicSharedMemorySize, SMEM_GEMM);
    cudaFuncSetAttribute(gemm_h_f16, cudaFuncAttributeMaxDynamicSharedMemorySize, SMEM_GEMM);

    init_deg_kernel<<<(NN + 255) / 256, 256>>>();
    deg_edges_kernel<<<(EE + 255) / 256, 256>>>(ei, ea);
    dinv_kernel<<<(NN + 255) / 256, 256>>>();
    agg_init_kernel<<<(NN * 48 + 255) / 256, 256>>>(x);
    {
        long long tot = (long long)EE * 48;
        int blocks = (int)((tot + 255) / 256);
        agg_edges_kernel<<<blocks, 256>>>(x, ei, ea);
    }
    weff_kernel<<<10, 256>>>(Wzg, bzg, Wzl, bzl, 0);
    weff_kernel<<<10, 256>>>(Wrg, brg, Wrl, brl, 1);
    weff_kernel<<<10, 256>>>(Whg, bhg, Whl, bhl, 2);
    softmax_att_kernel<<<1, 32>>>(att);
    zero_HA_kernel<<<(NN * CC + 255) / 256, 256>>>();
    prep_Bzr_h_kernel<<<(1024 * CC + 255) / 256, 256>>>(Wzl, Wrl);
    prep_Bh_h_kernel<<<(CC * CC + 255) / 256, 256>>>(Whl);

    dim3 gzr((NN + 127) / 128, 1024 / 128);   // 79 x 8
    dim3 gh((NN + 127) / 128, CC / 128);      // 79 x 4
    for (int t = 0; t < TT; ++t) {
        gemm_zr_f16<<<gzr, 256, SMEM_GEMM>>>(t);
        gemm_h_f16<<<gh, 256, SMEM_GEMM>>>(t);
    }
    dim3 g1((NN + 127) / 128, HIDN / 128);
    head1_tc<<<g1, 256>>>(W1, b1);
    head2_kernel<<<(NN * OUTD + 255) / 256, 256>>>(W2, b2, out);
    copy_acc_kernel<<<(NN * CC + 255) / 256, 256>>>(out);
}